// round 12
// baseline (speedup 1.0000x reference)
#include <cuda_runtime.h>
#include <cuda_bf16.h>
#include <math.h>
#include <stdint.h>

#define Bsz  256
#define Tsz  128
#define Hsz  1024
#define G3   3072
#define Vsz  348
#define Vpad 384
#define Kd   1024
#define NBLK 296                         // 2 CTAs per SM
#define NTHR 256
#define WSEG 3145728   // 3072*1024
#define BH   (Bsz * Hsz)

// GEMM unit: 128(m) x 64(n), BK=32, 256 threads = 8 warps (4m x 2n), warp tile 32x32
// 6-stage cp.async ring, one __syncthreads per 64-K region (2 chunks).
#define TM 128
#define TN 64
#define PITCH 80                         // smem row pitch bytes (32 bf16 + pad)
#define STAGE_BYTES ((TM + TN) * PITCH)  // 15360
#define NSTAGE 6
#define SMEM_DYN (NSTAGE * STAGE_BYTES + 256)   // 92416 per CTA; x2 = 184832 <= 228KB

// ---------------- scratch (device globals; no allocs allowed) ----------------
__device__ __nv_bfloat16  g_gi1[(size_t)Tsz * Bsz * G3];
__device__ __nv_bfloat16  g_xb[(size_t)Tsz * Bsz * Kd];
__device__ __nv_bfloat16  g_wb[6 * (size_t)WSEG];
__device__ __nv_bfloat16  g_wout[Vpad * Kd];
__device__ __nv_bfloat16  g_gh1[Bsz * G3];
__device__ __nv_bfloat16  g_gi2[Bsz * G3], g_gh2[Bsz * G3];
__device__ __nv_bfloat16  g_gi3[Bsz * G3], g_gh3[Bsz * G3];
__device__ float          g_h1[BH], g_h2[BH], g_h3[BH];
__device__ __nv_bfloat16  g_h1b[BH], g_h2b[BH], g_h3b[BH];
__device__ float          g_logits[2 * Bsz * Vpad];        // double-buffered by step parity
__device__ unsigned       g_bar_count;   // monotonic
__device__ unsigned       g_bar_gen;     // monotonic

namespace {
struct Boot {
    Boot() { void* p = nullptr; cudaGetSymbolAddress(&p, g_gi1); }
};
static Boot boot_;
}

// ---------------- low-level helpers ----------------
__device__ __forceinline__ uint32_t smem_u32(const void* p) {
    return (uint32_t)__cvta_generic_to_shared(p);
}
__device__ __forceinline__ void cpa16s(uint32_t saddr, const void* g) {
    asm volatile("cp.async.cg.shared.global [%0], [%1], 16;" :: "r"(saddr), "l"(g));
}
__device__ __forceinline__ void cpa_commit() {
    asm volatile("cp.async.commit_group;");
}
template <int N>
__device__ __forceinline__ void cpa_wait() {
    asm volatile("cp.async.wait_group %0;" :: "n"(N));
}
__device__ __forceinline__ void ldsm_x4(uint32_t* r, uint32_t a) {
    asm volatile("ldmatrix.sync.aligned.m8n8.x4.shared.b16 {%0,%1,%2,%3}, [%4];"
        : "=r"(r[0]), "=r"(r[1]), "=r"(r[2]), "=r"(r[3]) : "r"(a));
}
__device__ __forceinline__ void mma16816(float* c, const uint32_t* a, uint32_t b0, uint32_t b1) {
    asm volatile(
        "mma.sync.aligned.m16n8k16.row.col.f32.bf16.bf16.f32 "
        "{%0,%1,%2,%3},{%4,%5,%6,%7},{%8,%9},{%0,%1,%2,%3};"
        : "+f"(c[0]), "+f"(c[1]), "+f"(c[2]), "+f"(c[3])
        : "r"(a[0]), "r"(a[1]), "r"(a[2]), "r"(a[3]), "r"(b0), "r"(b1));
}
__device__ __forceinline__ void store_pair(float* p, float a, float b) {
    *(float2*)p = make_float2(a, b);
}
__device__ __forceinline__ void store_pair(__nv_bfloat16* p, float a, float b) {
    *(__nv_bfloat162*)p = __floats2bfloat162_rn(a, b);
}
__device__ __forceinline__ float2 bf2(const __nv_bfloat16* p) {
    __nv_bfloat162 v = *(const __nv_bfloat162*)p;
    return make_float2(__bfloat162float(v.x), __bfloat162float(v.y));
}

// ---------------- grid barrier (release/acquire, monotonic) ----------------
__device__ __forceinline__ void grid_barrier(unsigned& gen) {
    __syncthreads();
    if (threadIdx.x == 0) {
        unsigned target = gen + 1;
        unsigned old;
        asm volatile("atom.add.acq_rel.gpu.u32 %0, [%1], 1;"
                     : "=r"(old) : "l"(&g_bar_count) : "memory");
        if (old == target * NBLK - 1) {
            asm volatile("st.release.gpu.u32 [%0], %1;"
                         :: "l"(&g_bar_gen), "r"(target) : "memory");
        } else {
            unsigned cur;
            do {
                asm volatile("ld.acquire.gpu.u32 %0, [%1];"
                             : "=r"(cur) : "l"(&g_bar_gen) : "memory");
            } while (cur < target);
        }
    }
    gen++;
    __syncthreads();
}

// ---------------- mma.sync GEMM unit: C[128 x 64] = A[128xK] @ W[64xK]^T ----------------
// A bf16 [M][K] row-major; W bf16 [N][K] row-major (= B col-major for mma.row.col).
// 256 threads = 8 warps (4m x 2n), warp tile 32x32.
// 6-stage cp.async ring; one __syncthreads per 64-K region (2 x BK=32 sub-chunks).
template <typename CT>
__device__ __forceinline__ void mma_unit(
    const __nv_bfloat16* __restrict__ A,
    const __nv_bfloat16* __restrict__ W,
    CT* __restrict__ C, int ldC,
    int m0, int n0, uint32_t smem0)
{
    const int tid  = threadIdx.x;
    const int lane = tid & 31;
    const int wid  = tid >> 5;          // 0..7
    const int wm   = (wid & 3) * 32;    // warp m-slab
    const int wn   = (wid >> 2) * 32;   // warp n-slab

    // ---- per-thread cp.async mapping: i 0..1 -> A segs, i 2 -> W seg ----
    const char* baseA = (const char*)(A + (size_t)m0 * Kd);
    const char* baseW = (const char*)(W + (size_t)n0 * Kd);
    uint32_t s_off[3], g_off[3];
    #pragma unroll
    for (int i = 0; i < 2; i++) {        // A: 128 rows x 4 x 16B = 512 segs
        int seg = tid + i * NTHR;
        int row = seg >> 2, part = seg & 3;
        s_off[i] = row * PITCH + part * 16;
        g_off[i] = row * (Kd * 2) + part * 16;
    }
    {                                    // W: 64 rows x 4 x 16B = 256 segs
        int row = tid >> 2, part = tid & 3;
        s_off[2] = TM * PITCH + row * PITCH + part * 16;
        g_off[2] = row * (Kd * 2) + part * 16;
    }

    float acc[2][4][4];
    #pragma unroll
    for (int mi = 0; mi < 2; mi++)
        #pragma unroll
        for (int ni = 0; ni < 4; ni++)
            #pragma unroll
            for (int q = 0; q < 4; q++) acc[mi][ni][q] = 0.f;

    // ldmatrix lane address components (non-trans for both operands)
    const int a_r = (lane & 7) + (lane & 8);
    const int a_k = (lane >> 4) * 16;
    const int b_r = (lane & 7) + ((lane >> 4) << 3);
    const int b_k = (lane & 8) ? 16 : 0;

    auto issue = [&](int c) {
        uint32_t st = smem0 + (uint32_t)(c % NSTAGE) * STAGE_BYTES;
        uint32_t gadd = (uint32_t)c * 64;   // 32 bf16 = 64 bytes per chunk
        cpa16s(st + s_off[0], baseA + g_off[0] + gadd);
        cpa16s(st + s_off[1], baseA + g_off[1] + gadd);
        cpa16s(st + s_off[2], baseW + g_off[2] + gadd);
        cpa_commit();
    };
    issue(0); issue(1); issue(2); issue(3);

    #pragma unroll 1
    for (int cp = 0; cp < 16; cp++) {
        const int c0 = 2 * cp;
        if (cp < 15) cpa_wait<2>(); else cpa_wait<0>();
        __syncthreads();
        if (c0 + 4 < 32) issue(c0 + 4);
        if (c0 + 5 < 32) issue(c0 + 5);
        #pragma unroll
        for (int h = 0; h < 2; h++) {
            uint32_t st = smem0 + (uint32_t)((c0 + h) % NSTAGE) * STAGE_BYTES;
            uint32_t sB = st + TM * PITCH;
            #pragma unroll
            for (int ks = 0; ks < 2; ks++) {
                uint32_t a4[2][4], b4[2][4];
                #pragma unroll
                for (int mi = 0; mi < 2; mi++)
                    ldsm_x4(a4[mi], st + (wm + mi * 16 + a_r) * PITCH + a_k + ks * 32);
                #pragma unroll
                for (int bi = 0; bi < 2; bi++)
                    ldsm_x4(b4[bi], sB + (wn + bi * 16 + b_r) * PITCH + b_k + ks * 32);
                #pragma unroll
                for (int mi = 0; mi < 2; mi++)
                    #pragma unroll
                    for (int bi = 0; bi < 2; bi++) {
                        mma16816(acc[mi][2 * bi],     a4[mi], b4[bi][0], b4[bi][1]);
                        mma16816(acc[mi][2 * bi + 1], a4[mi], b4[bi][2], b4[bi][3]);
                    }
            }
        }
    }

    const int er = lane >> 2;
    const int ec = (lane & 3) * 2;
    #pragma unroll
    for (int mi = 0; mi < 2; mi++) {
        #pragma unroll
        for (int ni = 0; ni < 4; ni++) {
            CT* p = C + (size_t)(m0 + wm + mi * 16 + er) * ldC + n0 + wn + ni * 8 + ec;
            store_pair(p,           acc[mi][ni][0], acc[mi][ni][1]);
            store_pair(p + 8 * ldC, acc[mi][ni][2], acc[mi][ni][3]);
        }
    }
    __syncthreads();
}

// ---------------- phase helpers ----------------
__device__ __forceinline__ float sigmoidf_(float x) { return 1.f / (1.f + __expf(-x)); }

__device__ __forceinline__ void gate_phase(
    const __nv_bfloat16* __restrict__ gi, const __nv_bfloat16* __restrict__ gh,
    const float* __restrict__ bi, const float* __restrict__ bh,
    float* __restrict__ h, __nv_bfloat16* __restrict__ hb)
{
    const int NP = BH / 2;
    for (int p = blockIdx.x * blockDim.x + threadIdx.x;
         p < NP; p += gridDim.x * blockDim.x) {
        int b = p >> 9;
        int j = (p & 511) * 2;
        const __nv_bfloat16* gib = gi + (size_t)b * G3;
        const __nv_bfloat16* ghb = gh + (size_t)b * G3;
        float2 ir = bf2(gib + j), iz = bf2(gib + 1024 + j), in2 = bf2(gib + 2048 + j);
        float2 hr = bf2(ghb + j), hz = bf2(ghb + 1024 + j), hn = bf2(ghb + 2048 + j);
        float2 br0 = *(const float2*)(bi + j), bz0 = *(const float2*)(bi + 1024 + j),
               bn0 = *(const float2*)(bi + 2048 + j);
        float2 br1 = *(const float2*)(bh + j), bz1 = *(const float2*)(bh + 1024 + j),
               bn1 = *(const float2*)(bh + 2048 + j);
        int idx = b * Hsz + j;
        float2 hp = *(const float2*)(h + idx);

        float r0 = sigmoidf_(ir.x + br0.x + hr.x + br1.x);
        float z0 = sigmoidf_(iz.x + bz0.x + hz.x + bz1.x);
        float n0 = tanhf(in2.x + bn0.x + r0 * (hn.x + bn1.x));
        float h0 = (1.f - z0) * n0 + z0 * hp.x;

        float r1 = sigmoidf_(ir.y + br0.y + hr.y + br1.y);
        float z1 = sigmoidf_(iz.y + bz0.y + hz.y + bz1.y);
        float n1 = tanhf(in2.y + bn0.y + r1 * (hn.y + bn1.y));
        float h1 = (1.f - z1) * n1 + z1 * hp.y;

        *(float2*)(h + idx) = make_float2(h0, h1);
        *(__nv_bfloat162*)(hb + idx) = __floats2bfloat162_rn(h0, h1);
    }
}

// warp-per-row logprob; runs in the GEMM phase on one block (no __syncthreads)
__device__ __forceinline__ void logprob_warp(
    int t, int par, const int* __restrict__ target,
    const float* __restrict__ b_out, float* __restrict__ lp)
{
    const int lane = threadIdx.x & 31;
    const int wid  = threadIdx.x >> 5;          // 0..7
    const float* L = g_logits + (size_t)par * Bsz * Vpad;
    for (int b = wid; b < Bsz; b += NTHR / 32) {
        const float* row = L + (size_t)b * Vpad;
        float m = -1e30f;
        for (int v = lane; v < Vsz; v += 32) m = fmaxf(m, row[v] + b_out[v]);
        #pragma unroll
        for (int o = 16; o; o >>= 1) m = fmaxf(m, __shfl_xor_sync(0xffffffffu, m, o));
        float ss = 0.f;
        for (int v = lane; v < Vsz; v += 32) ss += __expf(row[v] + b_out[v] - m);
        #pragma unroll
        for (int o = 16; o; o >>= 1) ss += __shfl_xor_sync(0xffffffffu, ss, o);
        if (lane == 0) {
            int tg = target[b * Tsz + t];
            lp[b] += row[tg] + b_out[tg] - (m + __logf(ss));
        }
    }
}

// ---------------- unit dispatcher ----------------
// Unit ids: [0,576) = 6 GEMM groups x 96 subunits (2 m-tiles x 48 n-tiles of 128x64).
//   g=0 gh1(t=s), g=1 gi2(t=s-1), g=2 gh2(t=s-1), g=3 gi3(t=s-2), g=4 gh3(t=s-2),
//   g=5 gi1(t=s+1).
// [576,588) = logits (2 m-tiles x 6 n-tiles), t=s-3, parity s&1.
// 588 = logprob (t=s-4, parity (s-1)&1).
__device__ __forceinline__ void run_unit(
    int u, int s, uint32_t smem0,
    const int* __restrict__ target, const float* __restrict__ b_out,
    float* __restrict__ lp)
{
    if (u >= 589) return;
    if (u < 576) {
        const int g = u / 96, v = u % 96;
        const int m0 = (v / 48) * TM, n0 = (v % 48) * TN;
        switch (g) {
        case 0: if (s >= 0 && s < Tsz)
                    mma_unit(g_h1b, g_wb + 1 * (size_t)WSEG, g_gh1, G3, m0, n0, smem0);
                break;
        case 1: if (s >= 1 && s <= Tsz)
                    mma_unit(g_h1b, g_wb + 2 * (size_t)WSEG, g_gi2, G3, m0, n0, smem0);
                break;
        case 2: if (s >= 1 && s <= Tsz)
                    mma_unit(g_h2b, g_wb + 3 * (size_t)WSEG, g_gh2, G3, m0, n0, smem0);
                break;
        case 3: if (s >= 2 && s <= Tsz + 1)
                    mma_unit(g_h2b, g_wb + 4 * (size_t)WSEG, g_gi3, G3, m0, n0, smem0);
                break;
        case 4: if (s >= 2 && s <= Tsz + 1)
                    mma_unit(g_h3b, g_wb + 5 * (size_t)WSEG, g_gh3, G3, m0, n0, smem0);
                break;
        default: {
            int t1 = s + 1;
            if (t1 >= 0 && t1 < Tsz)
                mma_unit(g_xb + (size_t)t1 * Bsz * Kd, g_wb /* w_ih1 */,
                         g_gi1 + (size_t)t1 * Bsz * G3, G3, m0, n0, smem0);
        }       break;
        }
    } else if (u < 588) {
        const int v = u - 576;
        if (s >= 3 && s <= Tsz + 2)
            mma_unit(g_h3b, g_wout,
                     g_logits + (size_t)(s & 1) * Bsz * Vpad, Vpad,
                     (v / 6) * TM, (v % 6) * TN, smem0);
    } else {
        if (s >= 4 && s <= Tsz + 3)
            logprob_warp(s - 4, (s - 1) & 1, target, b_out, lp);
    }
}

// ---------------- persistent wavefront kernel (2 CTAs per SM) ----------------
__global__ __launch_bounds__(NTHR, 2) void recur_kernel(
    const int* __restrict__ target,
    const float* __restrict__ b_ih1, const float* __restrict__ b_hh1,
    const float* __restrict__ b_ih2, const float* __restrict__ b_hh2,
    const float* __restrict__ b_ih3, const float* __restrict__ b_hh3,
    const float* __restrict__ b_out,
    float* __restrict__ lp)
{
    extern __shared__ char dsm[];
    const uint32_t smem0 = (smem_u32(dsm) + 127u) & ~127u;
    unsigned gen = 0;
    const int u = blockIdx.x;

    for (int s = -1; s < Tsz + 4; s++) {
        // ---- GEMM phase: each block runs 2 units ----
        run_unit(u,        s, smem0, target, b_out, lp);
        run_unit(u + NBLK, s, smem0, target, b_out, lp);
        grid_barrier(gen);

        // ---- gate phase ----
        if (s >= 0 && s < Tsz)
            gate_phase(g_gi1 + (size_t)s * Bsz * G3, g_gh1, b_ih1, b_hh1, g_h1, g_h1b);
        if (s >= 1 && s <= Tsz)
            gate_phase(g_gi2, g_gh2, b_ih2, b_hh2, g_h2, g_h2b);
        if (s >= 2 && s <= Tsz + 1)
            gate_phase(g_gi3, g_gh3, b_ih3, b_hh3, g_h3, g_h3b);
        grid_barrier(gen);
    }
}

// ---------------- setup kernels ----------------
__global__ __launch_bounds__(256) void init_misc(const float* __restrict__ w_out,
                                                 float* __restrict__ lp)
{
    for (int i = blockIdx.x * blockDim.x + threadIdx.x;
         i < Vpad * Kd; i += gridDim.x * blockDim.x) {
        int row = i >> 10;
        g_wout[i] = (row < Vsz) ? __float2bfloat16(w_out[i]) : __float2bfloat16(0.f);
        if (i < BH) {
            g_h1[i] = 0.f; g_h2[i] = 0.f; g_h3[i] = 0.f;
            __nv_bfloat16 z = __float2bfloat16(0.f);
            g_h1b[i] = z; g_h2b[i] = z; g_h3b[i] = z;
        }
        if (i < Bsz) lp[i] = 0.f;
        if (i == 0) { g_bar_count = 0u; g_bar_gen = 0u; }
    }
}

__global__ __launch_bounds__(256) void conv_weights(
    const float* __restrict__ w0, const float* __restrict__ w1,
    const float* __restrict__ w2, const float* __restrict__ w3,
    const float* __restrict__ w4, const float* __restrict__ w5)
{
    for (size_t i = (size_t)blockIdx.x * blockDim.x + threadIdx.x;
         i < 6 * (size_t)WSEG; i += (size_t)gridDim.x * blockDim.x) {
        int seg = (int)(i / WSEG);
        size_t off = i % WSEG;
        const float* s = seg == 0 ? w0 : seg == 1 ? w1 : seg == 2 ? w2
                       : seg == 3 ? w3 : seg == 4 ? w4 : w5;
        g_wb[i] = __float2bfloat16(s[off]);
    }
}

__global__ __launch_bounds__(256) void gather_x(
    const int* __restrict__ target, const int* __restrict__ bosp,
    const float* __restrict__ emb)
{
    const int nq = Tsz * Bsz * (Kd / 4);
    for (int i = blockIdx.x * blockDim.x + threadIdx.x; i < nq; i += gridDim.x * blockDim.x) {
        int m  = i / (Kd / 4);
        int kq = i % (Kd / 4);
        int t = m >> 8, b = m & 255;
        int tok = (t == 0) ? bosp[0] : target[(b << 7) + t - 1];
        float4 v = *(const float4*)(emb + (size_t)tok * Kd + kq * 4);
        __nv_bfloat16* dst = g_xb + (size_t)m * Kd + kq * 4;
        *(__nv_bfloat162*)(dst)     = __floats2bfloat162_rn(v.x, v.y);
        *(__nv_bfloat162*)(dst + 2) = __floats2bfloat162_rn(v.z, v.w);
    }
}

// ---------------- launch ----------------
extern "C" void kernel_launch(void* const* d_in, const int* in_sizes, int n_in,
                              void* d_out, int out_size)
{
    (void)in_sizes; (void)n_in; (void)out_size;
    const int*   target = (const int*)  d_in[0];
    const int*   bos    = (const int*)  d_in[1];
    const float* emb    = (const float*)d_in[2];
    const float* w_ih1  = (const float*)d_in[3];
    const float* w_hh1  = (const float*)d_in[4];
    const float* b_ih1  = (const float*)d_in[5];
    const float* b_hh1  = (const float*)d_in[6];
    const float* w_ih2  = (const float*)d_in[7];
    const float* w_hh2  = (const float*)d_in[8];
    const float* b_ih2  = (const float*)d_in[9];
    const float* b_hh2  = (const float*)d_in[10];
    const float* w_ih3  = (const float*)d_in[11];
    const float* w_hh3  = (const float*)d_in[12];
    const float* b_ih3  = (const float*)d_in[13];
    const float* b_hh3  = (const float*)d_in[14];
    const float* w_out  = (const float*)d_in[15];
    const float* b_out  = (const float*)d_in[16];
    float* lp = (float*)d_out;

    cudaFuncSetAttribute(recur_kernel,
        cudaFuncAttributeMaxDynamicSharedMemorySize, SMEM_DYN);
    cudaFuncSetAttribute(recur_kernel,
        cudaFuncAttributePreferredSharedMemoryCarveout, 100);

    init_misc<<<(Vpad * Kd + 255) / 256, 256>>>(w_out, lp);
    conv_weights<<<8192, 256>>>(w_ih1, w_hh1, w_ih2, w_hh2, w_ih3, w_hh3);
    gather_x<<<8192, 256>>>(target, bos, emb);

    recur_kernel<<<NBLK, NTHR, SMEM_DYN>>>(target,
                                b_ih1, b_hh1, b_ih2, b_hh2, b_ih3, b_hh3,
                                b_out, lp);
}

// round 13
// speedup vs baseline: 1.5329x; 1.5329x over previous
#include <cuda_runtime.h>
#include <cuda_bf16.h>
#include <math.h>
#include <stdint.h>

#define Bsz  256
#define Tsz  128
#define Hsz  1024
#define G3   3072
#define Vsz  348
#define Vpad 384
#define Kd   1024
#define NBLK 148
#define NTHR 512
#define WSEG 3145728   // 3072*1024
#define BH   (Bsz * Hsz)

// GEMM config: BM=256 (=full M), BN=128, BK=32, 512 threads, warp tile 64x32
// 6-stage cp.async ring, ONE __syncthreads per 64-K region (2 chunks).
#define BM 256
#define BN 128
#define PITCH 80                         // smem row pitch bytes (32 bf16 + pad)
#define STAGE_BYTES ((BM + BN) * PITCH)  // 30720
#define NSTAGE 6
#define SMEM_DYN (NSTAGE * STAGE_BYTES + 256)   // 184832

// ---------------- scratch (device globals; no allocs allowed) ----------------
__device__ __nv_bfloat16  g_gi1[(size_t)Tsz * Bsz * G3];
__device__ __nv_bfloat16  g_xb[(size_t)Tsz * Bsz * Kd];
__device__ __nv_bfloat16  g_wb[6 * (size_t)WSEG];
__device__ __nv_bfloat16  g_wout[Vpad * Kd];
__device__ __nv_bfloat16  g_gh1[Bsz * G3];
__device__ __nv_bfloat16  g_gi2[Bsz * G3], g_gh2[Bsz * G3];
__device__ __nv_bfloat16  g_gi3[Bsz * G3], g_gh3[Bsz * G3];
__device__ float          g_h1[BH], g_h2[BH], g_h3[BH];
__device__ __nv_bfloat16  g_h1b[BH], g_h2b[BH], g_h3b[BH];
__device__ float          g_logits[2 * Bsz * Vpad];        // double-buffered by step parity
__device__ unsigned       g_bar_count;   // monotonic
__device__ unsigned       g_bar_gen;     // monotonic

namespace {
struct Boot {
    Boot() { void* p = nullptr; cudaGetSymbolAddress(&p, g_gi1); }
};
static Boot boot_;
}

// ---------------- low-level helpers ----------------
__device__ __forceinline__ uint32_t smem_u32(const void* p) {
    return (uint32_t)__cvta_generic_to_shared(p);
}
__device__ __forceinline__ void cpa16s(uint32_t saddr, const void* g) {
    asm volatile("cp.async.cg.shared.global [%0], [%1], 16;" :: "r"(saddr), "l"(g));
}
__device__ __forceinline__ void cpa_commit() {
    asm volatile("cp.async.commit_group;");
}
template <int N>
__device__ __forceinline__ void cpa_wait() {
    asm volatile("cp.async.wait_group %0;" :: "n"(N));
}
__device__ __forceinline__ void ldsm_x4(uint32_t* r, uint32_t a) {
    asm volatile("ldmatrix.sync.aligned.m8n8.x4.shared.b16 {%0,%1,%2,%3}, [%4];"
        : "=r"(r[0]), "=r"(r[1]), "=r"(r[2]), "=r"(r[3]) : "r"(a));
}
__device__ __forceinline__ void mma16816(float* c, const uint32_t* a, uint32_t b0, uint32_t b1) {
    asm volatile(
        "mma.sync.aligned.m16n8k16.row.col.f32.bf16.bf16.f32 "
        "{%0,%1,%2,%3},{%4,%5,%6,%7},{%8,%9},{%0,%1,%2,%3};"
        : "+f"(c[0]), "+f"(c[1]), "+f"(c[2]), "+f"(c[3])
        : "r"(a[0]), "r"(a[1]), "r"(a[2]), "r"(a[3]), "r"(b0), "r"(b1));
}
__device__ __forceinline__ void store_pair(float* p, float a, float b) {
    *(float2*)p = make_float2(a, b);
}
__device__ __forceinline__ void store_pair(__nv_bfloat16* p, float a, float b) {
    *(__nv_bfloat162*)p = __floats2bfloat162_rn(a, b);
}
__device__ __forceinline__ float2 bf2(const __nv_bfloat16* p) {
    __nv_bfloat162 v = *(const __nv_bfloat162*)p;
    return make_float2(__bfloat162float(v.x), __bfloat162float(v.y));
}
__device__ __forceinline__ float tanh_fast(float x) {
    float y; asm("tanh.approx.f32 %0, %1;" : "=f"(y) : "f"(x)); return y;
}

// ---------------- grid barrier (release/acquire, monotonic) ----------------
__device__ __forceinline__ void grid_barrier(unsigned& gen) {
    __syncthreads();
    if (threadIdx.x == 0) {
        unsigned target = gen + 1;
        unsigned old;
        asm volatile("atom.add.acq_rel.gpu.u32 %0, [%1], 1;"
                     : "=r"(old) : "l"(&g_bar_count) : "memory");
        if (old == target * NBLK - 1) {
            asm volatile("st.release.gpu.u32 [%0], %1;"
                         :: "l"(&g_bar_gen), "r"(target) : "memory");
        } else {
            unsigned cur;
            do {
                asm volatile("ld.acquire.gpu.u32 %0, [%1];"
                             : "=r"(cur) : "l"(&g_bar_gen) : "memory");
            } while (cur < target);
        }
    }
    gen++;
    __syncthreads();
}

// ---------------- mma.sync GEMM unit: C[256 x 128] = A[256xK] @ W[128xK]^T ----------------
// A bf16 [M][K] row-major; W bf16 [N][K] row-major (= B col-major for mma.row.col).
// 512 threads = 16 warps (4m x 4n), warp tile 64x32.
// 6-stage cp.async ring; one __syncthreads per 64-K region (2 x BK=32 sub-chunks).
template <typename CT>
__device__ __forceinline__ void mma_unit(
    const __nv_bfloat16* __restrict__ A,
    const __nv_bfloat16* __restrict__ W,
    CT* __restrict__ C, int ldC,
    int m0, int n0, uint32_t smem0)
{
    const int tid  = threadIdx.x;
    const int lane = tid & 31;
    const int wid  = tid >> 5;          // 0..15
    const int wm   = (wid & 3) * 64;    // warp m-slab
    const int wn   = (wid >> 2) * 32;   // warp n-slab

    const char* baseA = (const char*)(A + (size_t)m0 * Kd);
    const char* baseW = (const char*)(W + (size_t)n0 * Kd);
    uint32_t s_off[3], g_off[3];
    #pragma unroll
    for (int i = 0; i < 2; i++) {        // A: 256 rows x 4 x 16B = 1024 segs
        int seg = tid + i * NTHR;
        int row = seg >> 2, part = seg & 3;
        s_off[i] = row * PITCH + part * 16;
        g_off[i] = row * (Kd * 2) + part * 16;
    }
    {                                    // W: 128 rows x 4 x 16B = 512 segs
        int row = tid >> 2, part = tid & 3;
        s_off[2] = BM * PITCH + row * PITCH + part * 16;
        g_off[2] = row * (Kd * 2) + part * 16;
    }

    float acc[4][4][4];
    #pragma unroll
    for (int mi = 0; mi < 4; mi++)
        #pragma unroll
        for (int ni = 0; ni < 4; ni++)
            #pragma unroll
            for (int q = 0; q < 4; q++) acc[mi][ni][q] = 0.f;

    const int a_r = (lane & 7) + (lane & 8);
    const int a_k = (lane >> 4) * 16;
    const int b_r = (lane & 7) + ((lane >> 4) << 3);
    const int b_k = (lane & 8) ? 16 : 0;

    auto issue = [&](int c) {
        uint32_t st = smem0 + (uint32_t)(c % NSTAGE) * STAGE_BYTES;
        uint32_t gadd = (uint32_t)c * 64;   // 32 bf16 = 64 bytes per chunk
        cpa16s(st + s_off[0], baseA + g_off[0] + gadd);
        cpa16s(st + s_off[1], baseA + g_off[1] + gadd);
        cpa16s(st + s_off[2], baseW + g_off[2] + gadd);
        cpa_commit();
    };
    issue(0); issue(1); issue(2); issue(3);

    #pragma unroll 1
    for (int cp = 0; cp < 16; cp++) {
        const int c0 = 2 * cp;
        if (cp < 15) cpa_wait<2>(); else cpa_wait<0>();
        __syncthreads();
        if (c0 + 4 < 32) issue(c0 + 4);
        if (c0 + 5 < 32) issue(c0 + 5);
        #pragma unroll
        for (int h = 0; h < 2; h++) {
            uint32_t st = smem0 + (uint32_t)((c0 + h) % NSTAGE) * STAGE_BYTES;
            uint32_t sB = st + BM * PITCH;
            #pragma unroll
            for (int ks = 0; ks < 2; ks++) {
                uint32_t a4[4][4], b4[2][4];
                #pragma unroll
                for (int mi = 0; mi < 4; mi++)
                    ldsm_x4(a4[mi], st + (wm + mi * 16 + a_r) * PITCH + a_k + ks * 32);
                #pragma unroll
                for (int bi = 0; bi < 2; bi++)
                    ldsm_x4(b4[bi], sB + (wn + bi * 16 + b_r) * PITCH + b_k + ks * 32);
                #pragma unroll
                for (int mi = 0; mi < 4; mi++)
                    #pragma unroll
                    for (int bi = 0; bi < 2; bi++) {
                        mma16816(acc[mi][2 * bi],     a4[mi], b4[bi][0], b4[bi][1]);
                        mma16816(acc[mi][2 * bi + 1], a4[mi], b4[bi][2], b4[bi][3]);
                    }
            }
        }
    }

    const int er = lane >> 2;
    const int ec = (lane & 3) * 2;
    #pragma unroll
    for (int mi = 0; mi < 4; mi++) {
        #pragma unroll
        for (int ni = 0; ni < 4; ni++) {
            CT* p = C + (size_t)(m0 + wm + mi * 16 + er) * ldC + n0 + wn + ni * 8 + ec;
            store_pair(p,            acc[mi][ni][0], acc[mi][ni][1]);
            store_pair(p + 8 * ldC,  acc[mi][ni][2], acc[mi][ni][3]);
        }
    }
    __syncthreads();
}

// ---------------- phase helpers ----------------
__device__ __forceinline__ float sigmoidf_(float x) { return 1.f / (1.f + __expf(-x)); }

__device__ __forceinline__ void gate_phase(
    const __nv_bfloat16* __restrict__ gi, const __nv_bfloat16* __restrict__ gh,
    const float* __restrict__ bi, const float* __restrict__ bh,
    float* __restrict__ h, __nv_bfloat16* __restrict__ hb)
{
    const int NP = BH / 2;
    for (int p = blockIdx.x * blockDim.x + threadIdx.x;
         p < NP; p += gridDim.x * blockDim.x) {
        int b = p >> 9;
        int j = (p & 511) * 2;
        const __nv_bfloat16* gib = gi + (size_t)b * G3;
        const __nv_bfloat16* ghb = gh + (size_t)b * G3;
        float2 ir = bf2(gib + j), iz = bf2(gib + 1024 + j), in2 = bf2(gib + 2048 + j);
        float2 hr = bf2(ghb + j), hz = bf2(ghb + 1024 + j), hn = bf2(ghb + 2048 + j);
        float2 br0 = *(const float2*)(bi + j), bz0 = *(const float2*)(bi + 1024 + j),
               bn0 = *(const float2*)(bi + 2048 + j);
        float2 br1 = *(const float2*)(bh + j), bz1 = *(const float2*)(bh + 1024 + j),
               bn1 = *(const float2*)(bh + 2048 + j);
        int idx = b * Hsz + j;
        float2 hp = *(const float2*)(h + idx);

        float r0 = sigmoidf_(ir.x + br0.x + hr.x + br1.x);
        float z0 = sigmoidf_(iz.x + bz0.x + hz.x + bz1.x);
        float n0 = tanh_fast(in2.x + bn0.x + r0 * (hn.x + bn1.x));
        float h0 = (1.f - z0) * n0 + z0 * hp.x;

        float r1 = sigmoidf_(ir.y + br0.y + hr.y + br1.y);
        float z1 = sigmoidf_(iz.y + bz0.y + hz.y + bz1.y);
        float n1 = tanh_fast(in2.y + bn0.y + r1 * (hn.y + bn1.y));
        float h1 = (1.f - z1) * n1 + z1 * hp.y;

        *(float2*)(h + idx) = make_float2(h0, h1);
        *(__nv_bfloat162*)(hb + idx) = __floats2bfloat162_rn(h0, h1);
    }
}

// warp-per-row logprob; runs in the GEMM phase on block 147 (no __syncthreads)
__device__ __forceinline__ void logprob_warp(
    int t, int par, const int* __restrict__ target,
    const float* __restrict__ b_out, float* __restrict__ lp)
{
    const int lane = threadIdx.x & 31;
    const int wid  = threadIdx.x >> 5;          // 0..15
    const float* L = g_logits + (size_t)par * Bsz * Vpad;
    for (int b = wid; b < Bsz; b += 16) {
        const float* row = L + (size_t)b * Vpad;
        float m = -1e30f;
        for (int v = lane; v < Vsz; v += 32) m = fmaxf(m, row[v] + b_out[v]);
        #pragma unroll
        for (int o = 16; o; o >>= 1) m = fmaxf(m, __shfl_xor_sync(0xffffffffu, m, o));
        float ss = 0.f;
        for (int v = lane; v < Vsz; v += 32) ss += __expf(row[v] + b_out[v] - m);
        #pragma unroll
        for (int o = 16; o; o >>= 1) ss += __shfl_xor_sync(0xffffffffu, ss, o);
        if (lane == 0) {
            int tg = target[b * Tsz + t];
            lp[b] += row[tg] + b_out[tg] - (m + __logf(ss));
        }
    }
}

// ---------------- persistent wavefront kernel ----------------
// Super-step s GEMM phase (all independent):
//   gh1(t=s), gi2+gh2(t=s-1), gi3+gh3(t=s-2), logits(t=s-3) -> parity s&1,
//   gi1(t=s+1), and block 147: logprob(t=s-4) from parity (s-1)&1.
// Gate phase: gate1(s), gate2(s-1), gate3(s-2). 2 barriers/step.
__global__ __launch_bounds__(NTHR, 1) void recur_kernel(
    const int* __restrict__ target,
    const float* __restrict__ b_ih1, const float* __restrict__ b_hh1,
    const float* __restrict__ b_ih2, const float* __restrict__ b_hh2,
    const float* __restrict__ b_ih3, const float* __restrict__ b_hh3,
    const float* __restrict__ b_out,
    float* __restrict__ lp)
{
    extern __shared__ char dsm[];
    const uint32_t smem0 = (smem_u32(dsm) + 127u) & ~127u;
    unsigned gen = 0;
    const int u = blockIdx.x;

    for (int s = -1; s < Tsz + 4; s++) {
        // ---- GEMM phase ----
        if (u < 24) {
            if (s >= 0 && s < Tsz)
                mma_unit(g_h1b, g_wb + 1 * (size_t)WSEG, g_gh1, G3, 0, u * 128, smem0);
        } else if (u < 48) {
            if (s >= 1 && s <= Tsz)
                mma_unit(g_h1b, g_wb + 2 * (size_t)WSEG, g_gi2, G3, 0, (u - 24) * 128, smem0);
        } else if (u < 72) {
            if (s >= 1 && s <= Tsz)
                mma_unit(g_h2b, g_wb + 3 * (size_t)WSEG, g_gh2, G3, 0, (u - 48) * 128, smem0);
        } else if (u < 96) {
            if (s >= 2 && s <= Tsz + 1)
                mma_unit(g_h2b, g_wb + 4 * (size_t)WSEG, g_gi3, G3, 0, (u - 72) * 128, smem0);
        } else if (u < 120) {
            if (s >= 2 && s <= Tsz + 1)
                mma_unit(g_h3b, g_wb + 5 * (size_t)WSEG, g_gh3, G3, 0, (u - 96) * 128, smem0);
        } else if (u < 123) {
            if (s >= 3 && s <= Tsz + 2)
                mma_unit(g_h3b, g_wout,
                         g_logits + (size_t)(s & 1) * Bsz * Vpad, Vpad,
                         0, (u - 120) * 128, smem0);
        } else if (u < 147) {
            int tg1 = s + 1;                   // gi1 for the NEXT super-step
            if (tg1 >= 0 && tg1 < Tsz)
                mma_unit(g_xb + (size_t)tg1 * Bsz * Kd, g_wb /* w_ih1 */,
                         g_gi1 + (size_t)tg1 * Bsz * G3, G3, 0, (u - 123) * 128, smem0);
        } else {
            if (s >= 4 && s <= Tsz + 3)
                logprob_warp(s - 4, (s - 1) & 1, target, b_out, lp);
        }
        grid_barrier(gen);

        // ---- gate phase ----
        if (s >= 0 && s < Tsz)
            gate_phase(g_gi1 + (size_t)s * Bsz * G3, g_gh1, b_ih1, b_hh1, g_h1, g_h1b);
        if (s >= 1 && s <= Tsz)
            gate_phase(g_gi2, g_gh2, b_ih2, b_hh2, g_h2, g_h2b);
        if (s >= 2 && s <= Tsz + 1)
            gate_phase(g_gi3, g_gh3, b_ih3, b_hh3, g_h3, g_h3b);
        grid_barrier(gen);
    }
}

// ---------------- setup kernels ----------------
__global__ __launch_bounds__(256) void init_misc(const float* __restrict__ w_out,
                                                 float* __restrict__ lp)
{
    for (int i = blockIdx.x * blockDim.x + threadIdx.x;
         i < Vpad * Kd; i += gridDim.x * blockDim.x) {
        int row = i >> 10;
        g_wout[i] = (row < Vsz) ? __float2bfloat16(w_out[i]) : __float2bfloat16(0.f);
        if (i < BH) {
            g_h1[i] = 0.f; g_h2[i] = 0.f; g_h3[i] = 0.f;
            __nv_bfloat16 z = __float2bfloat16(0.f);
            g_h1b[i] = z; g_h2b[i] = z; g_h3b[i] = z;
        }
        if (i < Bsz) lp[i] = 0.f;
        if (i == 0) { g_bar_count = 0u; g_bar_gen = 0u; }
    }
}

__global__ __launch_bounds__(256) void conv_weights(
    const float* __restrict__ w0, const float* __restrict__ w1,
    const float* __restrict__ w2, const float* __restrict__ w3,
    const float* __restrict__ w4, const float* __restrict__ w5)
{
    for (size_t i = (size_t)blockIdx.x * blockDim.x + threadIdx.x;
         i < 6 * (size_t)WSEG; i += (size_t)gridDim.x * blockDim.x) {
        int seg = (int)(i / WSEG);
        size_t off = i % WSEG;
        const float* s = seg == 0 ? w0 : seg == 1 ? w1 : seg == 2 ? w2
                       : seg == 3 ? w3 : seg == 4 ? w4 : w5;
        g_wb[i] = __float2bfloat16(s[off]);
    }
}

__global__ __launch_bounds__(256) void gather_x(
    const int* __restrict__ target, const int* __restrict__ bosp,
    const float* __restrict__ emb)
{
    const int nq = Tsz * Bsz * (Kd / 4);
    for (int i = blockIdx.x * blockDim.x + threadIdx.x; i < nq; i += gridDim.x * blockDim.x) {
        int m  = i / (Kd / 4);
        int kq = i % (Kd / 4);
        int t = m >> 8, b = m & 255;
        int tok = (t == 0) ? bosp[0] : target[(b << 7) + t - 1];
        float4 v = *(const float4*)(emb + (size_t)tok * Kd + kq * 4);
        __nv_bfloat16* dst = g_xb + (size_t)m * Kd + kq * 4;
        *(__nv_bfloat162*)(dst)     = __floats2bfloat162_rn(v.x, v.y);
        *(__nv_bfloat162*)(dst + 2) = __floats2bfloat162_rn(v.z, v.w);
    }
}

// ---------------- launch ----------------
extern "C" void kernel_launch(void* const* d_in, const int* in_sizes, int n_in,
                              void* d_out, int out_size)
{
    (void)in_sizes; (void)n_in; (void)out_size;
    const int*   target = (const int*)  d_in[0];
    const int*   bos    = (const int*)  d_in[1];
    const float* emb    = (const float*)d_in[2];
    const float* w_ih1  = (const float*)d_in[3];
    const float* w_hh1  = (const float*)d_in[4];
    const float* b_ih1  = (const float*)d_in[5];
    const float* b_hh1  = (const float*)d_in[6];
    const float* w_ih2  = (const float*)d_in[7];
    const float* w_hh2  = (const float*)d_in[8];
    const float* b_ih2  = (const float*)d_in[9];
    const float* b_hh2  = (const float*)d_in[10];
    const float* w_ih3  = (const float*)d_in[11];
    const float* w_hh3  = (const float*)d_in[12];
    const float* b_ih3  = (const float*)d_in[13];
    const float* b_hh3  = (const float*)d_in[14];
    const float* w_out  = (const float*)d_in[15];
    const float* b_out  = (const float*)d_in[16];
    float* lp = (float*)d_out;

    cudaFuncSetAttribute(recur_kernel,
        cudaFuncAttributeMaxDynamicSharedMemorySize, SMEM_DYN);

    init_misc<<<(Vpad * Kd + 255) / 256, 256>>>(w_out, lp);
    conv_weights<<<8192, 256>>>(w_ih1, w_hh1, w_ih2, w_hh2, w_ih3, w_hh3);
    gather_x<<<8192, 256>>>(target, bos, emb);

    recur_kernel<<<NBLK, NTHR, SMEM_DYN>>>(target,
                                b_ih1, b_hh1, b_ih2, b_hh2, b_ih3, b_hh3,
                                b_out, lp);
}